// round 14
// baseline (speedup 1.0000x reference)
#include <cuda_runtime.h>
#include <cuda_bf16.h>
#include <cstdint>
#include <math.h>

#define S_LEN 2048
#define HDIM  4096
#define NHEADS 32
#define NKVH   8
#define HEADD  128
#define KVDIM  1024

typedef __nv_bfloat16 bf16;

// ---------------- scratch (static device globals; no allocations) ----------
__device__ float g_q[S_LEN * HDIM];
__device__ float g_k[S_LEN * KVDIM];
__device__ float g_v[S_LEN * KVDIM];
__device__ float g_o[S_LEN * HDIM];
__device__ float g_cos[S_LEN * 64];
__device__ float g_sin[S_LEN * 64];
// bf16 hi/lo panel-major planes (K -> panels of [R x 32])
__device__ bf16 g_xh[S_LEN * HDIM],  g_xl[S_LEN * HDIM];
__device__ bf16 g_wqh[HDIM * HDIM],  g_wql[HDIM * HDIM];
__device__ bf16 g_wkh[KVDIM * HDIM], g_wkl[KVDIM * HDIM];
__device__ bf16 g_wvh[KVDIM * HDIM], g_wvl[KVDIM * HDIM];
__device__ bf16 g_woh[HDIM * HDIM],  g_wol[HDIM * HDIM];
__device__ bf16 g_oh[S_LEN * HDIM],  g_ol[S_LEN * HDIM];
// pre-formatted KV tiles: [kvh][j][4 planes: Kh,Kl,Vh,Vl][64 rows x 272B]
#define PL      17408                 // 64 * 272
#define TILESZ  (4 * PL)              // 69632
__device__ uint4 g_kvt[(NKVH * 32 * TILESZ) / 16];

// ============================================================================
// helpers
// ============================================================================
__device__ __forceinline__ uint32_t smem_u32(const void* p) {
    uint32_t a;
    asm("{ .reg .u64 t; cvta.to.shared.u64 t, %1; cvt.u32.u64 %0, t; }"
        : "=r"(a) : "l"(p));
    return a;
}
__device__ __forceinline__ void ldmx4(uint32_t& r0, uint32_t& r1,
                                      uint32_t& r2, uint32_t& r3, uint32_t addr) {
    asm volatile("ldmatrix.sync.aligned.m8n8.x4.shared.b16 {%0,%1,%2,%3}, [%4];"
                 : "=r"(r0), "=r"(r1), "=r"(r2), "=r"(r3) : "r"(addr));
}
__device__ __forceinline__ void ldmx4t(uint32_t& r0, uint32_t& r1,
                                       uint32_t& r2, uint32_t& r3, uint32_t addr) {
    asm volatile("ldmatrix.sync.aligned.m8n8.x4.trans.shared.b16 {%0,%1,%2,%3}, [%4];"
                 : "=r"(r0), "=r"(r1), "=r"(r2), "=r"(r3) : "r"(addr));
}
__device__ __forceinline__ void mma16816(float* c, const uint32_t* a, const uint32_t* b) {
    asm volatile(
        "mma.sync.aligned.m16n8k16.row.col.f32.bf16.bf16.f32 "
        "{%0,%1,%2,%3}, {%4,%5,%6,%7}, {%8,%9}, {%0,%1,%2,%3};"
        : "+f"(c[0]), "+f"(c[1]), "+f"(c[2]), "+f"(c[3])
        : "r"(a[0]), "r"(a[1]), "r"(a[2]), "r"(a[3]), "r"(b[0]), "r"(b[1]));
}
__device__ __forceinline__ float ex2(float x) {
    float r;
    asm("ex2.approx.ftz.f32 %0, %1;" : "=f"(r) : "f"(x));
    return r;
}
__device__ __forceinline__ void split2(float x, float y, uint32_t& hi, uint32_t& lo) {
    bf16 hx = __float2bfloat16_rn(x);
    bf16 hy = __float2bfloat16_rn(y);
    bf16 lx = __float2bfloat16_rn(x - __bfloat162float(hx));
    bf16 ly = __float2bfloat16_rn(y - __bfloat162float(hy));
    __nv_bfloat162 H = {hx, hy}, L = {lx, ly};
    hi = *reinterpret_cast<uint32_t*>(&H);
    lo = *reinterpret_cast<uint32_t*>(&L);
}
__device__ __forceinline__ void cp16(uint32_t smem_dst, const void* gsrc) {
    asm volatile("cp.async.cg.shared.global [%0], [%1], 16;"
                 :: "r"(smem_dst), "l"(gsrc) : "memory");
}
#define CP_COMMIT() asm volatile("cp.async.commit_group;" ::: "memory")
#define CP_WAIT0()  asm volatile("cp.async.wait_group 0;" ::: "memory")
#define CP_WAIT1()  asm volatile("cp.async.wait_group 1;" ::: "memory")

// ============================================================================
// fp32 -> bf16 hi/lo, panel-major: plane[p*R*32 + r*32 + (k&31)], p = k>>5
// ============================================================================
__global__ __launch_bounds__(256) void convert_split(const float* __restrict__ src,
                                                     bf16* __restrict__ H,
                                                     bf16* __restrict__ L, int R)
{
    int idx = blockIdx.x * blockDim.x + threadIdx.x;
    if (idx >= R * 1024) return;
    int r = idx >> 10;
    int k4 = (idx & 1023) * 4;
    float4 v = *(const float4*)(src + (size_t)r * 4096 + k4);
    size_t off = (size_t)(k4 >> 5) * R * 32 + (size_t)r * 32 + (k4 & 31);
    uint32_t h0, l0, h1, l1;
    split2(v.x, v.y, h0, l0);
    split2(v.z, v.w, h1, l1);
    *(uint2*)(H + off) = make_uint2(h0, h1);
    *(uint2*)(L + off) = make_uint2(l0, l1);
}

// ============================================================================
// 3-stage cp.async pipelined bf16 split GEMM. BM=BN=128, BK=32, 256 thr.
// wait_group 1 at head (oldest stage only), issue stage it+2 after barrier.
// ============================================================================
#define PLSZ   10240
#define STAGESZ (4 * PLSZ)
#define GPIPE_SMEM (3 * STAGESZ)      // 122880

__device__ __forceinline__ void gemm_core(
    const bf16* __restrict__ Ahp, const bf16* __restrict__ Alp, int RA,
    const bf16* __restrict__ Bhp, const bf16* __restrict__ Blp, int RB,
    float* __restrict__ C, int Cs, int m0, int n0, char* sm)
{
    const uint32_t sb = smem_u32(sm);
    const int tid = threadIdx.x, lane = tid & 31, wid = tid >> 5;
    const int wr = wid >> 1, wc = wid & 1;

    const bf16* cur[8];
    uint32_t smoff[8];
    size_t pstr[8];
    {
        const bf16* gbase[4] = {Ahp + (size_t)m0 * 32, Alp + (size_t)m0 * 32,
                                Bhp + (size_t)n0 * 32, Blp + (size_t)n0 * 32};
        const size_t pstride[4] = {(size_t)RA * 32, (size_t)RA * 32,
                                   (size_t)RB * 32, (size_t)RB * 32};
#pragma unroll
        for (int j = 0; j < 8; j++) {
            int p = j >> 1;
            int cip = tid + 256 * (j & 1);
            cur[j] = gbase[p] + cip * 8;
            pstr[j] = pstride[p];
            smoff[j] = p * PLSZ + (cip >> 2) * 80 + (cip & 3) * 16;
        }
    }

    const uint32_t aA = sb + (wr * 32 + (lane & 15)) * 80 + ((lane >> 4) & 1) * 16;
    const uint32_t aB = sb + 2 * PLSZ +
        (wc * 64 + (lane & 7) + ((lane >> 4) & 1) * 8) * 80 + ((lane >> 3) & 1) * 16;

    float acc[2][8][4];
#pragma unroll
    for (int mt = 0; mt < 2; mt++)
#pragma unroll
        for (int nt = 0; nt < 8; nt++)
#pragma unroll
            for (int i = 0; i < 4; i++) acc[mt][nt][i] = 0.f;

    // prologue: stages 0 and 1
#pragma unroll
    for (int s = 0; s < 2; s++) {
#pragma unroll
        for (int j = 0; j < 8; j++) {
            cp16(sb + (uint32_t)s * STAGESZ + smoff[j], cur[j]);
            cur[j] += pstr[j];
        }
        CP_COMMIT();
    }

    uint32_t stg = 0, nstg = 2 * STAGESZ;
    const int NK = 128;
    for (int it = 0; it < NK; ++it) {
        if (it + 1 < NK) { CP_WAIT1(); } else { CP_WAIT0(); }
        __syncthreads();   // stage `it` ready everywhere; buffer `nstg` free
        if (it + 2 < NK) {
#pragma unroll
            for (int j = 0; j < 8; j++) {
                cp16(sb + nstg + smoff[j], cur[j]);
                cur[j] += pstr[j];
            }
            CP_COMMIT();
        }

#pragma unroll
        for (int ks = 0; ks < 2; ks++) {
            const uint32_t ko = stg + ks * 32;
            uint32_t Ah[2][4], Al[2][4];
#pragma unroll
            for (int mt = 0; mt < 2; mt++) {
                ldmx4(Ah[mt][0], Ah[mt][1], Ah[mt][2], Ah[mt][3], aA + ko + mt * 16 * 80);
                ldmx4(Al[mt][0], Al[mt][1], Al[mt][2], Al[mt][3],
                      aA + ko + PLSZ + mt * 16 * 80);
            }
#pragma unroll
            for (int np = 0; np < 4; np++) {
                uint32_t Bh[4], Bl[4];
                ldmx4(Bh[0], Bh[1], Bh[2], Bh[3], aB + ko + np * 16 * 80);
                ldmx4(Bl[0], Bl[1], Bl[2], Bl[3], aB + ko + PLSZ + np * 16 * 80);
#pragma unroll
                for (int mt = 0; mt < 2; mt++) {
                    mma16816(acc[mt][2*np],   Ah[mt], Bh);
                    mma16816(acc[mt][2*np],   Ah[mt], Bl);
                    mma16816(acc[mt][2*np],   Al[mt], Bh);
                    mma16816(acc[mt][2*np+1], Ah[mt], Bh + 2);
                    mma16816(acc[mt][2*np+1], Ah[mt], Bl + 2);
                    mma16816(acc[mt][2*np+1], Al[mt], Bh + 2);
                }
            }
        }

        stg  += STAGESZ; if (stg  == 3 * STAGESZ) stg  = 0;
        nstg += STAGESZ; if (nstg == 3 * STAGESZ) nstg = 0;
    }

    const int gid = lane >> 2, tig = lane & 3;
#pragma unroll
    for (int mt = 0; mt < 2; mt++) {
        const int row = m0 + wr * 32 + mt * 16 + gid;
#pragma unroll
        for (int nt = 0; nt < 8; nt++) {
            const int col = n0 + wc * 64 + nt * 8 + tig * 2;
            *(float2*)(C + (size_t)row * Cs + col) =
                make_float2(acc[mt][nt][0], acc[mt][nt][1]);
            *(float2*)(C + (size_t)(row + 8) * Cs + col) =
                make_float2(acc[mt][nt][2], acc[mt][nt][3]);
        }
    }
}

__global__ __launch_bounds__(256) void gemm_qkv(float* __restrict__ qo,
                                                float* __restrict__ ko,
                                                float* __restrict__ vo)
{
    extern __shared__ char sm[];
    const int bx = blockIdx.x, by = blockIdx.y;
    const bf16 *Bh, *Bl; float* C; int Cs, RB, nb;
    if (bx < 32)      { Bh = g_wqh; Bl = g_wql; C = qo; Cs = 4096; RB = 4096; nb = bx; }
    else if (bx < 40) { Bh = g_wkh; Bl = g_wkl; C = ko; Cs = 1024; RB = 1024; nb = bx - 32; }
    else              { Bh = g_wvh; Bl = g_wvl; C = vo; Cs = 1024; RB = 1024; nb = bx - 40; }
    gemm_core(g_xh, g_xl, 2048, Bh, Bl, RB, C, Cs, by * 128, nb * 128, sm);
}

__global__ __launch_bounds__(256) void gemm_wo(float* __restrict__ out)
{
    extern __shared__ char sm[];
    gemm_core(g_oh, g_ol, 2048, g_woh, g_wol, 4096, out, 4096,
              blockIdx.y * 128, blockIdx.x * 128, sm);
}

// ---------------------------------------------------------------------------
// RoPE table (pow hoisted, fp64 range-reduce + fp32 sin/cos) + apply (Q only)
// ---------------------------------------------------------------------------
__global__ void rope_table()
{
    __shared__ double sinv[64];
    if (threadIdx.x < 64)
        sinv[threadIdx.x] = pow(500000.0, -(double)threadIdx.x / 64.0);
    __syncthreads();
    int idx = blockIdx.x * blockDim.x + threadIdx.x;
    if (idx >= S_LEN * 64) return;
    int s = idx >> 6, i = idx & 63;
    double a = fmod((double)s * sinv[i], 6.283185307179586476925286766559);
    float fa = (float)a;
    g_cos[idx] = cosf(fa);
    g_sin[idx] = sinf(fa);
}

__global__ void rope_apply(float* __restrict__ buf, int nheads)
{
    int idx = blockIdx.x * blockDim.x + threadIdx.x;
    int total = S_LEN * nheads * 64;
    if (idx >= total) return;
    int i = idx & 63;
    int h = (idx >> 6) % nheads;
    int s = idx / (nheads * 64);
    float c  = g_cos[s * 64 + i];
    float sn = g_sin[s * 64 + i];
    float* p = buf + (size_t)s * nheads * HEADD + h * HEADD;
    float x0 = p[i];
    float x1 = p[i + 64];
    p[i]      = x0 * c - x1 * sn;
    p[i + 64] = x1 * c + x0 * sn;
}

// ============================================================================
// kv_prep: K (RoPE'd) + V -> bf16 hi/lo smem-image tiles in gmem.
// ============================================================================
__global__ __launch_bounds__(256) void kv_prep()
{
    int t = blockIdx.x * 256 + threadIdx.x;
    int q = t & 3, kvh = (t >> 2) & 7, s = t >> 5;
    const float* kp = g_k + (size_t)s * KVDIM + kvh * HEADD + q * 32;
    const float* pp = g_k + (size_t)s * KVDIM + kvh * HEADD + (q ^ 2) * 32;
    const float* vp = g_v + (size_t)s * KVDIM + kvh * HEADD + q * 32;
    const float* cp_ = g_cos + (size_t)s * 64 + (q & 1) * 32;
    const float* sp_ = g_sin + (size_t)s * 64 + (q & 1) * 32;
    const float sgn = (q < 2) ? -1.f : 1.f;
    const int j = s >> 6, r = s & 63;
    char* tb = (char*)g_kvt + (size_t)(kvh * 32 + j) * TILESZ + r * 272 + q * 64;
    char* kh = tb;
    char* kl = tb + PL;
    char* vh = tb + 2 * PL;
    char* vl = tb + 3 * PL;
#pragma unroll
    for (int c = 0; c < 8; c++) {
        float4 x  = ((const float4*)kp)[c];
        float4 px = ((const float4*)pp)[c];
        float4 cc = ((const float4*)cp_)[c];
        float4 sv = ((const float4*)sp_)[c];
        x.x = x.x * cc.x + sgn * px.x * sv.x;
        x.y = x.y * cc.y + sgn * px.y * sv.y;
        x.z = x.z * cc.z + sgn * px.z * sv.z;
        x.w = x.w * cc.w + sgn * px.w * sv.w;
        uint32_t h0, l0, h1, l1;
        split2(x.x, x.y, h0, l0);
        split2(x.z, x.w, h1, l1);
        ((uint2*)kh)[c] = make_uint2(h0, h1);
        ((uint2*)kl)[c] = make_uint2(l0, l1);
        x = ((const float4*)vp)[c];
        split2(x.x, x.y, h0, l0);
        split2(x.z, x.w, h1, l1);
        ((uint2*)vh)[c] = make_uint2(h0, h1);
        ((uint2*)vl)[c] = make_uint2(l0, l1);
    }
}

// ============================================================================
// Tensor-core flash attention: Q fp32 load+scale+split, KV via cp.async
// double-buffer from pre-formatted tiles. (R11-validated)
// ============================================================================
#define FQHo 0
#define FQLo 34816
#define SKV0 69632
#define FA3_SMEM (69632 + 2 * TILESZ)    // 208896

__global__ __launch_bounds__(256) void flash_mma(const float* __restrict__ Q,
                                                 float* __restrict__ O)
{
    extern __shared__ char sm[];
    const uint32_t sb = smem_u32(sm);
    const int tid = threadIdx.x, lane = tid & 31, wid = tid >> 5;
    const int h = blockIdx.y;
    const int bxr = (int)gridDim.x - 1 - (int)blockIdx.x;   // heavy blocks first
    const int m0 = bxr * 128;
    const int kvh = h >> 2;
    const float qscale = 0.0883883476483184f * 1.4426950408889634f;

    {
        int row = tid >> 1, half = tid & 1;
        const float* qp = Q + (size_t)(m0 + row) * HDIM + h * HEADD + half * 64;
        char* dh = sm + FQHo + row * 272 + half * 128;
        char* dl = sm + FQLo + row * 272 + half * 128;
#pragma unroll
        for (int c = 0; c < 16; c++) {
            float4 v = ((const float4*)qp)[c];
            v.x *= qscale; v.y *= qscale; v.z *= qscale; v.w *= qscale;
            uint32_t h0, l0, h1, l1;
            split2(v.x, v.y, h0, l0);
            split2(v.z, v.w, h1, l1);
            ((uint2*)dh)[c] = make_uint2(h0, h1);
            ((uint2*)dl)[c] = make_uint2(l0, l1);
        }
    }

    float o[16][4];
#pragma unroll
    for (int dt = 0; dt < 16; dt++)
#pragma unroll
        for (int i = 0; i < 4; i++) o[dt][i] = 0.f;
    float mA = -1e30f, mB = -1e30f, lA = 0.f, lB = 0.f;

    const int wrow0 = m0 + wid * 16;
    const uint32_t aQh = sb + FQHo + (wid * 16 + (lane & 15)) * 272 + ((lane >> 4) & 1) * 16;
    const uint32_t aQl = aQh + (FQLo - FQHo);
    const uint32_t relK = ((lane & 7) + ((lane >> 4) & 1) * 8) * 272 + ((lane >> 3) & 1) * 16;
    const uint32_t relV = ((lane & 7) + ((lane >> 3) & 1) * 8) * 272 + ((lane >> 4) & 1) * 16;

    const char* blob = (const char*)g_kvt + (size_t)(kvh * 32) * TILESZ;
    const int jmax = 2 * bxr + 1;

    {
        const char* src = blob + tid * 16;
        const uint32_t dst = sb + SKV0 + tid * 16;
#pragma unroll
        for (int i = 0; i < 17; i++) cp16(dst + i * 4096, src + i * 4096);
        CP_COMMIT();
    }

    for (int j = 0; j <= jmax; j++) {
        const int n0 = j * 64;
        const uint32_t stg = SKV0 + (uint32_t)(j & 1) * TILESZ;
        CP_WAIT0();
        __syncthreads();
        if (j + 1 <= jmax) {
            const char* src = blob + (size_t)(j + 1) * TILESZ + tid * 16;
            const uint32_t dst = sb + SKV0 + (uint32_t)((j + 1) & 1) * TILESZ + tid * 16;
#pragma unroll
            for (int i = 0; i < 17; i++) cp16(dst + i * 4096, src + i * 4096);
            CP_COMMIT();
        }

        if (n0 > wrow0 + 15) continue;

        const uint32_t aKh = sb + stg + relK;
        const uint32_t aKl = aKh + PL;
        const uint32_t aVh = sb + stg + 2 * PL + relV;
        const uint32_t aVl = aVh + PL;

        float s[8][4];
#pragma unroll
        for (int t = 0; t < 8; t++)
#pragma unroll
            for (int i = 0; i < 4; i++) s[t][i] = 0.f;

#pragma unroll
        for (int kc = 0; kc < 8; kc++) {
            uint32_t qh[4], ql[4];
            ldmx4(qh[0], qh[1], qh[2], qh[3], aQh + kc * 32);
            ldmx4(ql[0], ql[1], ql[2], ql[3], aQl + kc * 32);
#pragma unroll
            for (int np = 0; np < 4; np++) {
                uint32_t kh[4], kl[4];
                ldmx4(kh[0], kh[1], kh[2], kh[3], aKh + np * 16 * 272 + kc * 32);
                ldmx4(kl[0], kl[1], kl[2], kl[3], aKl + np * 16 * 272 + kc * 32);
                mma16816(s[2*np],   qh, kh);
                mma16816(s[2*np],   qh, kl);
                mma16816(s[2*np],   ql, kh);
                mma16816(s[2*np+1], qh, kh + 2);
                mma16816(s[2*np+1], qh, kl + 2);
                mma16816(s[2*np+1], ql, kh + 2);
            }
        }

        const int rA = wrow0 + (lane >> 2);
        const int rB = rA + 8;
        const int cb = n0 + 2 * (lane & 3);
        if (n0 + 63 > wrow0) {
#pragma unroll
            for (int t = 0; t < 8; t++) {
                int c0 = cb + 8 * t;
                if (c0     > rA) s[t][0] = -1e30f;
                if (c0 + 1 > rA) s[t][1] = -1e30f;
                if (c0     > rB) s[t][2] = -1e30f;
                if (c0 + 1 > rB) s[t][3] = -1e30f;
            }
        }

        float xA = -1e30f, xB = -1e30f;
#pragma unroll
        for (int t = 0; t < 8; t++) {
            xA = fmaxf(xA, fmaxf(s[t][0], s[t][1]));
            xB = fmaxf(xB, fmaxf(s[t][2], s[t][3]));
        }
        xA = fmaxf(xA, __shfl_xor_sync(0xffffffffu, xA, 1));
        xA = fmaxf(xA, __shfl_xor_sync(0xffffffffu, xA, 2));
        xB = fmaxf(xB, __shfl_xor_sync(0xffffffffu, xB, 1));
        xB = fmaxf(xB, __shfl_xor_sync(0xffffffffu, xB, 2));
        float mAn = fmaxf(mA, xA), mBn = fmaxf(mB, xB);
        float cA = ex2(mA - mAn), cB = ex2(mB - mBn);
        mA = mAn; mB = mBn;
        float sumA = 0.f, sumB = 0.f;
#pragma unroll
        for (int t = 0; t < 8; t++) {
            s[t][0] = ex2(s[t][0] - mA); sumA += s[t][0];
            s[t][1] = ex2(s[t][1] - mA); sumA += s[t][1];
            s[t][2] = ex2(s[t][2] - mB); sumB += s[t][2];
            s[t][3] = ex2(s[t][3] - mB); sumB += s[t][3];
        }
        sumA += __shfl_xor_sync(0xffffffffu, sumA, 1);
        sumA += __shfl_xor_sync(0xffffffffu, sumA, 2);
        sumB += __shfl_xor_sync(0xffffffffu, sumB, 1);
        sumB += __shfl_xor_sync(0xffffffffu, sumB, 2);
        lA = lA * cA + sumA;
        lB = lB * cB + sumB;
#pragma unroll
        for (int dt = 0; dt < 16; dt++) {
            o[dt][0] *= cA; o[dt][1] *= cA;
            o[dt][2] *= cB; o[dt][3] *= cB;
        }

#pragma unroll
        for (int kc = 0; kc < 4; kc++) {
            uint32_t ph[4], pl[4];
            split2(s[2*kc][0],   s[2*kc][1],   ph[0], pl[0]);
            split2(s[2*kc][2],   s[2*kc][3],   ph[1], pl[1]);
            split2(s[2*kc+1][0], s[2*kc+1][1], ph[2], pl[2]);
            split2(s[2*kc+1][2], s[2*kc+1][3], ph[3], pl[3]);
#pragma unroll
            for (int dp = 0; dp < 8; dp++) {
                uint32_t vh[4], vl[4];
                ldmx4t(vh[0], vh[1], vh[2], vh[3], aVh + kc * 16 * 272 + dp * 32);
                ldmx4t(vl[0], vl[1], vl[2], vl[3], aVl + kc * 16 * 272 + dp * 32);
                mma16816(o[2*dp],   ph, vh);
                mma16816(o[2*dp],   ph, vl);
                mma16816(o[2*dp],   pl, vh);
                mma16816(o[2*dp+1], ph, vh + 2);
                mma16816(o[2*dp+1], ph, vl + 2);
                mma16816(o[2*dp+1], pl, vh + 2);
            }
        }
    }

    const float ilA = 1.f / lA, ilB = 1.f / lB;
    const int rA = wrow0 + (lane >> 2);
    const int colb = h * HEADD + 2 * (lane & 3);
#pragma unroll
    for (int dt = 0; dt < 16; dt++) {
        *(float2*)(O + (size_t)rA * HDIM + colb + 8 * dt) =
            make_float2(o[dt][0] * ilA, o[dt][1] * ilA);
        *(float2*)(O + (size_t)(rA + 8) * HDIM + colb + 8 * dt) =
            make_float2(o[dt][2] * ilB, o[dt][3] * ilB);
    }
}

// ---------------------------------------------------------------------------
extern "C" void kernel_launch(void* const* d_in, const int* in_sizes, int n_in,
                              void* d_out, int out_size)
{
    const float* x  = (const float*)d_in[0];
    const float* wq = (const float*)d_in[1];
    const float* wk = (const float*)d_in[2];
    const float* wv = (const float*)d_in[3];
    const float* wo = (const float*)d_in[4];
    float* out = (float*)d_out;

    float *qb, *kb, *vb, *ob;
    cudaGetSymbolAddress((void**)&qb, g_q);
    cudaGetSymbolAddress((void**)&kb, g_k);
    cudaGetSymbolAddress((void**)&vb, g_v);
    cudaGetSymbolAddress((void**)&ob, g_o);
    bf16 *xh, *xl, *wqh, *wql, *wkh, *wkl, *wvh, *wvl, *woh, *wol, *oh, *ol;
    cudaGetSymbolAddress((void**)&xh,  g_xh);  cudaGetSymbolAddress((void**)&xl,  g_xl);
    cudaGetSymbolAddress((void**)&wqh, g_wqh); cudaGetSymbolAddress((void**)&wql, g_wql);
    cudaGetSymbolAddress((void**)&wkh, g_wkh); cudaGetSymbolAddress((void**)&wkl, g_wkl);
    cudaGetSymbolAddress((void**)&wvh, g_wvh); cudaGetSymbolAddress((void**)&wvl, g_wvl);
    cudaGetSymbolAddress((void**)&woh, g_woh); cudaGetSymbolAddress((void**)&wol, g_wol);
    cudaGetSymbolAddress((void**)&oh,  g_oh);  cudaGetSymbolAddress((void**)&ol,  g_ol);

    cudaFuncSetAttribute(flash_mma, cudaFuncAttributeMaxDynamicSharedMemorySize, FA3_SMEM);
    cudaFuncSetAttribute(gemm_qkv,  cudaFuncAttributeMaxDynamicSharedMemorySize, GPIPE_SMEM);
    cudaFuncSetAttribute(gemm_wo,   cudaFuncAttributeMaxDynamicSharedMemorySize, GPIPE_SMEM);

    rope_table<<<(S_LEN * 64) / 256, 256>>>();                        // 1
    convert_split<<<(2048 * 1024) / 256, 256>>>(x,  xh,  xl,  2048);  // 2
    convert_split<<<(4096 * 1024) / 256, 256>>>(wq, wqh, wql, 4096);  // 3
    convert_split<<<(1024 * 1024) / 256, 256>>>(wk, wkh, wkl, 1024);  // 4
    convert_split<<<(1024 * 1024) / 256, 256>>>(wv, wvh, wvl, 1024);  // 5

    gemm_qkv<<<dim3(48, 16), 256, GPIPE_SMEM>>>(qb, kb, vb);          // 6

    convert_split<<<(4096 * 1024) / 256, 256>>>(wo, woh, wol, 4096);  // 7
    rope_apply<<<(S_LEN * NHEADS * 64) / 256, 256>>>(qb, NHEADS);     // 8
    kv_prep<<<256, 256>>>();                                          // 9
    flash_mma<<<dim3(S_LEN / 128, NHEADS), 256, FA3_SMEM>>>(qb, ob);  // 10
    convert_split<<<(2048 * 1024) / 256, 256>>>(ob, oh, ol, 2048);    // 11
    gemm_wo<<<dim3(32, 16), 256, GPIPE_SMEM>>>(out);                  // 12
}

// round 15
// speedup vs baseline: 1.1980x; 1.1980x over previous
#include <cuda_runtime.h>
#include <cuda_bf16.h>
#include <cstdint>
#include <math.h>

#define S_LEN 2048
#define HDIM  4096
#define NHEADS 32
#define NKVH   8
#define HEADD  128
#define KVDIM  1024

typedef __nv_bfloat16 bf16;

// ---------------- scratch (static device globals; no allocations) ----------
__device__ float g_q[S_LEN * HDIM];
__device__ float g_k[S_LEN * KVDIM];
__device__ float g_v[S_LEN * KVDIM];
__device__ float g_o[S_LEN * HDIM];
__device__ float g_cos[S_LEN * 64];
__device__ float g_sin[S_LEN * 64];
// A-side planes (x, o): MMA-fragment layout [mb][kc][lane][4 regs] (16B/thread)
// B-side planes (weights): panel-major [p][r][32]
__device__ bf16 g_xh[S_LEN * HDIM],  g_xl[S_LEN * HDIM];
__device__ bf16 g_wqh[HDIM * HDIM],  g_wql[HDIM * HDIM];
__device__ bf16 g_wkh[KVDIM * HDIM], g_wkl[KVDIM * HDIM];
__device__ bf16 g_wvh[KVDIM * HDIM], g_wvl[KVDIM * HDIM];
__device__ bf16 g_woh[HDIM * HDIM],  g_wol[HDIM * HDIM];
__device__ bf16 g_oh[S_LEN * HDIM],  g_ol[S_LEN * HDIM];
// pre-formatted KV tiles: [kvh][j][4 planes: Kh,Kl,Vh,Vl][64 rows x 272B]
#define PL      17408
#define TILESZ  (4 * PL)
__device__ uint4 g_kvt[(NKVH * 32 * TILESZ) / 16];

// ============================================================================
// helpers
// ============================================================================
__device__ __forceinline__ uint32_t smem_u32(const void* p) {
    uint32_t a;
    asm("{ .reg .u64 t; cvta.to.shared.u64 t, %1; cvt.u32.u64 %0, t; }"
        : "=r"(a) : "l"(p));
    return a;
}
__device__ __forceinline__ void ldmx4(uint32_t& r0, uint32_t& r1,
                                      uint32_t& r2, uint32_t& r3, uint32_t addr) {
    asm volatile("ldmatrix.sync.aligned.m8n8.x4.shared.b16 {%0,%1,%2,%3}, [%4];"
                 : "=r"(r0), "=r"(r1), "=r"(r2), "=r"(r3) : "r"(addr));
}
__device__ __forceinline__ void ldmx4t(uint32_t& r0, uint32_t& r1,
                                       uint32_t& r2, uint32_t& r3, uint32_t addr) {
    asm volatile("ldmatrix.sync.aligned.m8n8.x4.trans.shared.b16 {%0,%1,%2,%3}, [%4];"
                 : "=r"(r0), "=r"(r1), "=r"(r2), "=r"(r3) : "r"(addr));
}
__device__ __forceinline__ void mma16816(float* c, const uint32_t* a, const uint32_t* b) {
    asm volatile(
        "mma.sync.aligned.m16n8k16.row.col.f32.bf16.bf16.f32 "
        "{%0,%1,%2,%3}, {%4,%5,%6,%7}, {%8,%9}, {%0,%1,%2,%3};"
        : "+f"(c[0]), "+f"(c[1]), "+f"(c[2]), "+f"(c[3])
        : "r"(a[0]), "r"(a[1]), "r"(a[2]), "r"(a[3]), "r"(b[0]), "r"(b[1]));
}
__device__ __forceinline__ float ex2(float x) {
    float r;
    asm("ex2.approx.ftz.f32 %0, %1;" : "=f"(r) : "f"(x));
    return r;
}
__device__ __forceinline__ void split2(float x, float y, uint32_t& hi, uint32_t& lo) {
    bf16 hx = __float2bfloat16_rn(x);
    bf16 hy = __float2bfloat16_rn(y);
    bf16 lx = __float2bfloat16_rn(x - __bfloat162float(hx));
    bf16 ly = __float2bfloat16_rn(y - __bfloat162float(hy));
    __nv_bfloat162 H = {hx, hy}, L = {lx, ly};
    hi = *reinterpret_cast<uint32_t*>(&H);
    lo = *reinterpret_cast<uint32_t*>(&L);
}
__device__ __forceinline__ void cp16(uint32_t smem_dst, const void* gsrc) {
    asm volatile("cp.async.cg.shared.global [%0], [%1], 16;"
                 :: "r"(smem_dst), "l"(gsrc) : "memory");
}
#define CP_COMMIT() asm volatile("cp.async.commit_group;" ::: "memory")
#define CP_WAIT0()  asm volatile("cp.async.wait_group 0;" ::: "memory")

// ============================================================================
// convert_split: fp32 -> bf16 hi/lo, panel-major (B-side / weights)
// ============================================================================
__global__ __launch_bounds__(256) void convert_split(const float* __restrict__ src,
                                                     bf16* __restrict__ H,
                                                     bf16* __restrict__ L, int R)
{
    int idx = blockIdx.x * blockDim.x + threadIdx.x;
    if (idx >= R * 1024) return;
    int r = idx >> 10;
    int k4 = (idx & 1023) * 4;
    float4 v = *(const float4*)(src + (size_t)r * 4096 + k4);
    size_t off = (size_t)(k4 >> 5) * R * 32 + (size_t)r * 32 + (k4 & 31);
    uint32_t h0, l0, h1, l1;
    split2(v.x, v.y, h0, l0);
    split2(v.z, v.w, h1, l1);
    *(uint2*)(H + off) = make_uint2(h0, h1);
    *(uint2*)(L + off) = make_uint2(l0, l1);
}

// ============================================================================
// convert_afrag: fp32 -> bf16 hi/lo in MMA A-fragment layout (A-side: x, o).
// Thread t -> (mb, kc, lane): writes uint4 (a0,a1,a2,a3) at byte t*16.
//   a0=(gid,2tig) a1=(gid+8,2tig) a2=(gid,2tig+8) a3=(gid+8,2tig+8)
// ============================================================================
__global__ __launch_bounds__(256) void convert_afrag(const float* __restrict__ src,
                                                     bf16* __restrict__ H,
                                                     bf16* __restrict__ L, int R)
{
    int t = blockIdx.x * 256 + threadIdx.x;
    if (t >= (R >> 4) * 256 * 32) return;
    int lane = t & 31;
    int kc = (t >> 5) & 255;
    int mb = t >> 13;
    int gid = lane >> 2, tig = lane & 3;
    const float* p0 = src + (size_t)(mb * 16 + gid) * 4096 + kc * 16 + tig * 2;
    float2 e0 = *(const float2*)(p0);
    float2 e1 = *(const float2*)(p0 + 8 * 4096);
    float2 e2 = *(const float2*)(p0 + 8);
    float2 e3 = *(const float2*)(p0 + 8 * 4096 + 8);
    uint4 Hv, Lv;
    split2(e0.x, e0.y, Hv.x, Lv.x);
    split2(e1.x, e1.y, Hv.y, Lv.y);
    split2(e2.x, e2.y, Hv.z, Lv.z);
    split2(e3.x, e3.y, Hv.w, Lv.w);
    *(uint4*)((char*)H + (size_t)t * 16) = Hv;
    *(uint4*)((char*)L + (size_t)t * 16) = Lv;
}

// ============================================================================
// A-direct GEMM: A fragments via LDG.128 from fragment-layout planes (no smem),
// B via 2-stage cp.async + LDSM (stride-80). BM=BN=128, BK=32, 256 thr, 2 CTA/SM.
// ============================================================================
#define BPL   10240                  // B plane bytes/stage: 128 rows * 80B
#define BSTG  (2 * BPL)              // Bh + Bl
#define GAD_SMEM (2 * BSTG)          // 40960

__device__ __forceinline__ void gemm_core_ad(
    const bf16* __restrict__ Ahf, const bf16* __restrict__ Alf,
    const bf16* __restrict__ Bhp, const bf16* __restrict__ Blp, int RB,
    float* __restrict__ C, int Cs, int m0, int n0, char* sm)
{
    const uint32_t sb = smem_u32(sm);
    const int tid = threadIdx.x, lane = tid & 31, wid = tid >> 5;
    const int wr = wid >> 1, wc = wid & 1;

    // B loader: 4 cp.async chunks of 16B per thread (2 per plane)
    const bf16* cur[4];
    uint32_t smoff[4];
    const size_t pstr = (size_t)RB * 32;
    {
        const bf16* gbase[2] = {Bhp + (size_t)n0 * 32, Blp + (size_t)n0 * 32};
#pragma unroll
        for (int j = 0; j < 4; j++) {
            int p = j >> 1;
            int cip = tid + 256 * (j & 1);
            cur[j] = gbase[p] + cip * 8;
            smoff[j] = p * BPL + (cip >> 2) * 80 + (cip & 3) * 16;
        }
    }

    // A fragment pointers (per mt): base + kc*512B
    const char* aH[2];
    const char* aL[2];
#pragma unroll
    for (int mt = 0; mt < 2; mt++) {
        size_t boff = ((size_t)((m0 >> 4) + wr * 2 + mt) * 256) * 512 + (size_t)lane * 16;
        aH[mt] = (const char*)Ahf + boff;
        aL[mt] = (const char*)Alf + boff;
    }

    const uint32_t aB = sb + (wc * 64 + (lane & 7) + ((lane >> 4) & 1) * 8) * 80
                      + ((lane >> 3) & 1) * 16;

    float acc[2][8][4];
#pragma unroll
    for (int mt = 0; mt < 2; mt++)
#pragma unroll
        for (int nt = 0; nt < 8; nt++)
#pragma unroll
            for (int i = 0; i < 4; i++) acc[mt][nt][i] = 0.f;

    // prologue: B stage 0; A kc=0 into prefetch buffer
#pragma unroll
    for (int j = 0; j < 4; j++) { cp16(sb + smoff[j], cur[j]); cur[j] += pstr; }
    CP_COMMIT();
    uint4 Anh[2], Anl[2];
#pragma unroll
    for (int mt = 0; mt < 2; mt++) {
        Anh[mt] = *(const uint4*)(aH[mt]);
        Anl[mt] = *(const uint4*)(aL[mt]);
    }
    int kcn = 1;

    const int NK = 128;
    for (int it = 0; it < NK; ++it) {
        const uint32_t stg = (uint32_t)(it & 1) * BSTG;
        CP_WAIT0();
        __syncthreads();
        if (it + 1 < NK) {
            const uint32_t nstg = (uint32_t)((it + 1) & 1) * BSTG;
#pragma unroll
            for (int j = 0; j < 4; j++) { cp16(sb + nstg + smoff[j], cur[j]); cur[j] += pstr; }
            CP_COMMIT();
        }

#pragma unroll
        for (int ks = 0; ks < 2; ks++) {
            uint4 Ah[2] = {Anh[0], Anh[1]};
            uint4 Al[2] = {Anl[0], Anl[1]};
            if (kcn < 256) {
#pragma unroll
                for (int mt = 0; mt < 2; mt++) {
                    Anh[mt] = *(const uint4*)(aH[mt] + (size_t)kcn * 512);
                    Anl[mt] = *(const uint4*)(aL[mt] + (size_t)kcn * 512);
                }
            }
            kcn++;
            const uint32_t ko = stg + ks * 32;
#pragma unroll
            for (int np = 0; np < 4; np++) {
                uint32_t Bh[4], Bl[4];
                ldmx4(Bh[0], Bh[1], Bh[2], Bh[3], aB + ko + np * 16 * 80);
                ldmx4(Bl[0], Bl[1], Bl[2], Bl[3], aB + ko + BPL + np * 16 * 80);
#pragma unroll
                for (int mt = 0; mt < 2; mt++) {
                    const uint32_t* ah = (const uint32_t*)&Ah[mt];
                    const uint32_t* al = (const uint32_t*)&Al[mt];
                    mma16816(acc[mt][2*np],   ah, Bh);
                    mma16816(acc[mt][2*np],   ah, Bl);
                    mma16816(acc[mt][2*np],   al, Bh);
                    mma16816(acc[mt][2*np+1], ah, Bh + 2);
                    mma16816(acc[mt][2*np+1], ah, Bl + 2);
                    mma16816(acc[mt][2*np+1], al, Bh + 2);
                }
            }
        }
    }

    const int gid = lane >> 2, tig = lane & 3;
#pragma unroll
    for (int mt = 0; mt < 2; mt++) {
        const int row = m0 + wr * 32 + mt * 16 + gid;
#pragma unroll
        for (int nt = 0; nt < 8; nt++) {
            const int col = n0 + wc * 64 + nt * 8 + tig * 2;
            *(float2*)(C + (size_t)row * Cs + col) =
                make_float2(acc[mt][nt][0], acc[mt][nt][1]);
            *(float2*)(C + (size_t)(row + 8) * Cs + col) =
                make_float2(acc[mt][nt][2], acc[mt][nt][3]);
        }
    }
}

__global__ __launch_bounds__(256, 2) void gemm_q(float* __restrict__ qo)
{
    extern __shared__ char sm[];
    gemm_core_ad(g_xh, g_xl, g_wqh, g_wql, 4096, qo, 4096,
                 blockIdx.y * 128, blockIdx.x * 128, sm);
}
__global__ __launch_bounds__(256, 2) void gemm_kv(float* __restrict__ ko,
                                                  float* __restrict__ vo)
{
    extern __shared__ char sm[];
    const int bx = blockIdx.x;
    if (bx < 8)
        gemm_core_ad(g_xh, g_xl, g_wkh, g_wkl, 1024, ko, 1024,
                     blockIdx.y * 128, bx * 128, sm);
    else
        gemm_core_ad(g_xh, g_xl, g_wvh, g_wvl, 1024, vo, 1024,
                     blockIdx.y * 128, (bx - 8) * 128, sm);
}
__global__ __launch_bounds__(256, 2) void gemm_wo(float* __restrict__ out)
{
    extern __shared__ char sm[];
    gemm_core_ad(g_oh, g_ol, g_woh, g_wol, 4096, out, 4096,
                 blockIdx.y * 128, blockIdx.x * 128, sm);
}

// ---------------------------------------------------------------------------
// RoPE table (pow hoisted, fp64 range-reduce + fp32 sin/cos) + apply (Q only)
// ---------------------------------------------------------------------------
__global__ void rope_table()
{
    __shared__ double sinv[64];
    if (threadIdx.x < 64)
        sinv[threadIdx.x] = pow(500000.0, -(double)threadIdx.x / 64.0);
    __syncthreads();
    int idx = blockIdx.x * blockDim.x + threadIdx.x;
    if (idx >= S_LEN * 64) return;
    int s = idx >> 6, i = idx & 63;
    double a = fmod((double)s * sinv[i], 6.283185307179586476925286766559);
    float fa = (float)a;
    g_cos[idx] = cosf(fa);
    g_sin[idx] = sinf(fa);
}

__global__ void rope_apply(float* __restrict__ buf, int nheads)
{
    int idx = blockIdx.x * blockDim.x + threadIdx.x;
    int total = S_LEN * nheads * 64;
    if (idx >= total) return;
    int i = idx & 63;
    int h = (idx >> 6) % nheads;
    int s = idx / (nheads * 64);
    float c  = g_cos[s * 64 + i];
    float sn = g_sin[s * 64 + i];
    float* p = buf + (size_t)s * nheads * HEADD + h * HEADD;
    float x0 = p[i];
    float x1 = p[i + 64];
    p[i]      = x0 * c - x1 * sn;
    p[i + 64] = x1 * c + x0 * sn;
}

// ============================================================================
// kv_prep: K (RoPE'd) + V -> bf16 hi/lo smem-image tiles in gmem.
// ============================================================================
__global__ __launch_bounds__(256) void kv_prep()
{
    int t = blockIdx.x * 256 + threadIdx.x;
    int q = t & 3, kvh = (t >> 2) & 7, s = t >> 5;
    const float* kp = g_k + (size_t)s * KVDIM + kvh * HEADD + q * 32;
    const float* pp = g_k + (size_t)s * KVDIM + kvh * HEADD + (q ^ 2) * 32;
    const float* vp = g_v + (size_t)s * KVDIM + kvh * HEADD + q * 32;
    const float* cp_ = g_cos + (size_t)s * 64 + (q & 1) * 32;
    const float* sp_ = g_sin + (size_t)s * 64 + (q & 1) * 32;
    const float sgn = (q < 2) ? -1.f : 1.f;
    const int j = s >> 6, r = s & 63;
    char* tb = (char*)g_kvt + (size_t)(kvh * 32 + j) * TILESZ + r * 272 + q * 64;
    char* kh = tb;
    char* kl = tb + PL;
    char* vh = tb + 2 * PL;
    char* vl = tb + 3 * PL;
#pragma unroll
    for (int c = 0; c < 8; c++) {
        float4 x  = ((const float4*)kp)[c];
        float4 px = ((const float4*)pp)[c];
        float4 cc = ((const float4*)cp_)[c];
        float4 sv = ((const float4*)sp_)[c];
        x.x = x.x * cc.x + sgn * px.x * sv.x;
        x.y = x.y * cc.y + sgn * px.y * sv.y;
        x.z = x.z * cc.z + sgn * px.z * sv.z;
        x.w = x.w * cc.w + sgn * px.w * sv.w;
        uint32_t h0, l0, h1, l1;
        split2(x.x, x.y, h0, l0);
        split2(x.z, x.w, h1, l1);
        ((uint2*)kh)[c] = make_uint2(h0, h1);
        ((uint2*)kl)[c] = make_uint2(l0, l1);
        x = ((const float4*)vp)[c];
        split2(x.x, x.y, h0, l0);
        split2(x.z, x.w, h1, l1);
        ((uint2*)vh)[c] = make_uint2(h0, h1);
        ((uint2*)vl)[c] = make_uint2(l0, l1);
    }
}

// ============================================================================
// Tensor-core flash attention (R11/R12-validated, unchanged)
// ============================================================================
#define FQHo 0
#define FQLo 34816
#define SKV0 69632
#define FA3_SMEM (69632 + 2 * TILESZ)

__global__ __launch_bounds__(256) void flash_mma(const float* __restrict__ Q,
                                                 float* __restrict__ O)
{
    extern __shared__ char sm[];
    const uint32_t sb = smem_u32(sm);
    const int tid = threadIdx.x, lane = tid & 31, wid = tid >> 5;
    const int h = blockIdx.y;
    const int bxr = (int)gridDim.x - 1 - (int)blockIdx.x;
    const int m0 = bxr * 128;
    const int kvh = h >> 2;
    const float qscale = 0.0883883476483184f * 1.4426950408889634f;

    {
        int row = tid >> 1, half = tid & 1;
        const float* qp = Q + (size_t)(m0 + row) * HDIM + h * HEADD + half * 64;
        char* dh = sm + FQHo + row * 272 + half * 128;
        char* dl = sm + FQLo + row * 272 + half * 128;
#pragma unroll
        for (int c = 0; c < 16; c++) {
            float4 v = ((const float4*)qp)[c];
            v.x *= qscale; v.y *= qscale; v.z *= qscale; v.w *= qscale;
            uint32_t h0, l0, h1, l1;
            split2(v.x, v.y, h0, l0);
            split2(v.z, v.w, h1, l1);
            ((uint2*)dh)[c] = make_uint2(h0, h1);
            ((uint2*)dl)[c] = make_uint2(l0, l1);
        }
    }

    float o[16][4];
#pragma unroll
    for (int dt = 0; dt < 16; dt++)
#pragma unroll
        for (int i = 0; i < 4; i++) o[dt][i] = 0.f;
    float mA = -1e30f, mB = -1e30f, lA = 0.f, lB = 0.f;

    const int wrow0 = m0 + wid * 16;
    const uint32_t aQh = sb + FQHo + (wid * 16 + (lane & 15)) * 272 + ((lane >> 4) & 1) * 16;
    const uint32_t aQl = aQh + (FQLo - FQHo);
    const uint32_t relK = ((lane & 7) + ((lane >> 4) & 1) * 8) * 272 + ((lane >> 3) & 1) * 16;
    const uint32_t relV = ((lane & 7) + ((lane >> 3) & 1) * 8) * 272 + ((lane >> 4) & 1) * 16;

    const char* blob = (const char*)g_kvt + (size_t)(kvh * 32) * TILESZ;
    const int jmax = 2 * bxr + 1;

    {
        const char* src = blob + tid * 16;
        const uint32_t dst = sb + SKV0 + tid * 16;
#pragma unroll
        for (int i = 0; i < 17; i++) cp16(dst + i * 4096, src + i * 4096);
        CP_COMMIT();
    }

    for (int j = 0; j <= jmax; j++) {
        const int n0 = j * 64;
        const uint32_t stg = SKV0 + (uint32_t)(j & 1) * TILESZ;
        CP_WAIT0();
        __syncthreads();
        if (j + 1 <= jmax) {
            const char* src = blob + (size_t)(j + 1) * TILESZ + tid * 16;
            const uint32_t dst = sb + SKV0 + (uint32_t)((j + 1) & 1) * TILESZ + tid * 16;
#pragma unroll
            for (int i = 0; i < 17; i++) cp16(dst + i * 4096, src + i * 4096);
            CP_COMMIT();
        }

        if (n0 > wrow0 + 15) continue;

        const uint32_t aKh = sb + stg + relK;
        const uint32_t aKl = aKh + PL;
        const uint32_t aVh = sb + stg + 2 * PL + relV;
        const uint32_t aVl = aVh + PL;

        float s[8][4];
#pragma unroll
        for (int t = 0; t < 8; t++)
#pragma unroll
            for (int i = 0; i < 4; i++) s[t][i] = 0.f;

#pragma unroll
        for (int kc = 0; kc < 8; kc++) {
            uint32_t qh[4], ql[4];
            ldmx4(qh[0], qh[1], qh[2], qh[3], aQh + kc * 32);
            ldmx4(ql[0], ql[1], ql[2], ql[3], aQl + kc * 32);
#pragma unroll
            for (int np = 0; np < 4; np++) {
                uint32_t kh[4], kl[4];
                ldmx4(kh[0], kh[1], kh[2], kh[3], aKh + np * 16 * 272 + kc * 32);
                ldmx4(kl[0], kl[1], kl[2], kl[3], aKl + np * 16 * 272 + kc * 32);
                mma16816(s[2*np],   qh, kh);
                mma16816(s[2*np],   qh, kl);
                mma16816(s[2*np],   ql, kh);
                mma16816(s[2*np+1], qh, kh + 2);
                mma16816(s[2*np+1], qh, kl + 2);
                mma16816(s[2*np+1], ql, kh + 2);
            }
        }

        const int rA = wrow0 + (lane >> 2);
        const int rB = rA + 8;
        const int cb = n0 + 2 * (lane & 3);
        if (n0 + 63 > wrow0) {
#pragma unroll
            for (int t = 0; t < 8; t++) {
                int c0 = cb + 8 * t;
                if (c0     > rA) s[t][0] = -1e30f;
                if (c0 + 1 > rA) s[t][1] = -1e30f;
                if (c0     > rB) s[t][2] = -1e30f;
                if (c0 + 1 > rB) s[t][3] = -1e30f;
            }
        }

        float xA = -1e30f, xB = -1e30f;
#pragma unroll
        for (int t = 0; t < 8; t++) {
            xA = fmaxf(xA, fmaxf(s[t][0], s[t][1]));
            xB = fmaxf(xB, fmaxf(s[t][2], s[t][3]));
        }
        xA = fmaxf(xA, __shfl_xor_sync(0xffffffffu, xA, 1));
        xA = fmaxf(xA, __shfl_xor_sync(0xffffffffu, xA, 2));
        xB = fmaxf(xB, __shfl_xor_sync(0xffffffffu, xB, 1));
        xB = fmaxf(xB, __shfl_xor_sync(0xffffffffu, xB, 2));
        float mAn = fmaxf(mA, xA), mBn = fmaxf(mB, xB);
        float cA = ex2(mA - mAn), cB = ex2(mB - mBn);
        mA = mAn; mB = mBn;
        float sumA = 0.f, sumB = 0.f;
#pragma unroll
        for (int t = 0; t < 8; t++) {
            s[t][0] = ex2(s[t][0] - mA); sumA += s[t][0];
            s[t][1] = ex2(s[t][1] - mA); sumA += s[t][1];
            s[t][2] = ex2(s[t][2] - mB); sumB += s[t][2];
            s[t][3] = ex2(s[t][3] - mB); sumB += s[t][3];
        }
        sumA += __shfl_xor_sync(0xffffffffu, sumA, 1);
        sumA += __shfl_xor_sync(0xffffffffu, sumA, 2);
        sumB += __shfl_xor_sync(0xffffffffu, sumB, 1);
        sumB += __shfl_xor_sync(0xffffffffu, sumB, 2);
        lA = lA * cA + sumA;
        lB = lB * cB + sumB;
#pragma unroll
        for (int dt = 0; dt < 16; dt++) {
            o[dt][0] *= cA; o[dt][1] *= cA;
            o[dt][2] *= cB; o[dt][3] *= cB;
        }

#pragma unroll
        for (int kc = 0; kc < 4; kc++) {
            uint32_t ph[4], pl[4];
            split2(s[2*kc][0],   s[2*kc][1],   ph[0], pl[0]);
            split2(s[2*kc][2],   s[2*kc][3],   ph[1], pl[1]);
            split2(s[2*kc+1][0], s[2*kc+1][1], ph[2], pl[2]);
            split2(s[2*kc+1][2], s[2*kc+1][3], ph[3], pl[3]);
#pragma unroll
            for (int dp = 0; dp < 8; dp++) {
                uint32_t vh[4], vl[4];
                ldmx4t(vh[0], vh[1], vh[2], vh[3], aVh + kc * 16 * 272 + dp * 32);
                ldmx4t(vl[0], vl[1], vl[2], vl[3], aVl + kc * 16 * 272 + dp * 32);
                mma16816(o[2*dp],   ph, vh);
                mma16816(o[2*dp],   ph, vl);
                mma16816(o[2*dp],   pl, vh);
                mma16816(o[2*dp+1], ph, vh + 2);
                mma16816(o[2*dp+1], ph, vl + 2);
                mma16816(o[2*dp+1], pl, vh + 2);
            }
        }
    }

    const float ilA = 1.f / lA, ilB = 1.f / lB;
    const int rA = wrow0 + (lane >> 2);
    const int colb = h * HEADD + 2 * (lane & 3);
#pragma unroll
    for (int dt = 0; dt < 16; dt++) {
        *(float2*)(O + (size_t)rA * HDIM + colb + 8 * dt) =
            make_float2(o[dt][0] * ilA, o[dt][1] * ilA);
        *(float2*)(O + (size_t)(rA + 8) * HDIM + colb + 8 * dt) =
            make_float2(o[dt][2] * ilB, o[dt][3] * ilB);
    }
}

// ---------------------------------------------------------------------------
extern "C" void kernel_launch(void* const* d_in, const int* in_sizes, int n_in,
                              void* d_out, int out_size)
{
    const float* x  = (const float*)d_in[0];
    const float* wq = (const float*)d_in[1];
    const float* wk = (const float*)d_in[2];
    const float* wv = (const float*)d_in[3];
    const float* wo = (const float*)d_in[4];
    float* out = (float*)d_out;

    float *qb, *kb, *vb, *ob;
    cudaGetSymbolAddress((void**)&qb, g_q);
    cudaGetSymbolAddress((void**)&kb, g_k);
    cudaGetSymbolAddress((void**)&vb, g_v);
    cudaGetSymbolAddress((void**)&ob, g_o);
    bf16 *xh, *xl, *wqh, *wql, *wkh, *wkl, *wvh, *wvl, *woh, *wol, *oh, *ol;
    cudaGetSymbolAddress((void**)&xh,  g_xh);  cudaGetSymbolAddress((void**)&xl,  g_xl);
    cudaGetSymbolAddress((void**)&wqh, g_wqh); cudaGetSymbolAddress((void**)&wql, g_wql);
    cudaGetSymbolAddress((void**)&wkh, g_wkh); cudaGetSymbolAddress((void**)&wkl, g_wkl);
    cudaGetSymbolAddress((void**)&wvh, g_wvh); cudaGetSymbolAddress((void**)&wvl, g_wvl);
    cudaGetSymbolAddress((void**)&woh, g_woh); cudaGetSymbolAddress((void**)&wol, g_wol);
    cudaGetSymbolAddress((void**)&oh,  g_oh);  cudaGetSymbolAddress((void**)&ol,  g_ol);

    cudaFuncSetAttribute(flash_mma, cudaFuncAttributeMaxDynamicSharedMemorySize, FA3_SMEM);
    cudaFuncSetAttribute(gemm_q,  cudaFuncAttributeMaxDynamicSharedMemorySize, GAD_SMEM);
    cudaFuncSetAttribute(gemm_kv, cudaFuncAttributeMaxDynamicSharedMemorySize, GAD_SMEM);
    cudaFuncSetAttribute(gemm_wo, cudaFuncAttributeMaxDynamicSharedMemorySize, GAD_SMEM);

    // Launch order: GEMMs at positions 5 & 6 so ncu (-s 5 -c 1) captures one.
    convert_afrag<<<4096, 256>>>(x,  xh,  xl,  2048);                 // 1
    convert_split<<<(4096 * 1024) / 256, 256>>>(wq, wqh, wql, 4096);  // 2
    convert_split<<<(1024 * 1024) / 256, 256>>>(wk, wkh, wkl, 1024);  // 3
    convert_split<<<(1024 * 1024) / 256, 256>>>(wv, wvh, wvl, 1024);  // 4

    gemm_q<<<dim3(32, 16), 256, GAD_SMEM>>>(qb);                      // 5
    gemm_kv<<<dim3(16, 16), 256, GAD_SMEM>>>(kb, vb);                 // 6

    rope_table<<<(S_LEN * 64) / 256, 256>>>();                        // 7
    convert_split<<<(4096 * 1024) / 256, 256>>>(wo, woh, wol, 4096);  // 8
    rope_apply<<<(S_LEN * NHEADS * 64) / 256, 256>>>(qb, NHEADS);     // 9
    kv_prep<<<256, 256>>>();                                          // 10
    flash_mma<<<dim3(S_LEN / 128, NHEADS), 256, FA3_SMEM>>>(qb, ob);  // 11
    convert_afrag<<<4096, 256>>>(ob, oh, ol, 2048);                   // 12
    gemm_wo<<<dim3(32, 16), 256, GAD_SMEM>>>(out);                    // 13
}